// round 7
// baseline (speedup 1.0000x reference)
#include <cuda_runtime.h>

#define MAX_B 8192

// Device-global scratch (no allocations). g_losses fully overwritten each
// launch; g_count reset by the last block so graph replays see clean state.
__device__ float g_losses[MAX_B];
__device__ unsigned int g_count;

// One block per row (B=8192, D=4096). Streaming: 8 front-batched LDG.128
// per thread, 3-way reduce, one STG per block, one counter atomic per block.
// The last-finishing block reduces all row losses and writes the mean.
__global__ void __launch_bounds__(256)
contrastive_fused_kernel(const float4* __restrict__ o1,
                         const float4* __restrict__ o2,
                         const int* __restrict__ tgt,  // int32 (jnp int64 w/o x64)
                         float* __restrict__ out,
                         int B, int d4 /* 1024 */) {
    const int row = blockIdx.x;
    const size_t base = (size_t)row * (size_t)d4;

    // Front-batch all loads: 4 float4 per array per thread -> 8 LDG.128 in flight.
    float4 a0, a1v, a2v, a3;
    float4 b0, b1v, b2v, b3;
    {
        const int j = threadIdx.x;
        a0  = o1[base + j];
        a1v = o1[base + j + 256];
        a2v = o1[base + j + 512];
        a3  = o1[base + j + 768];
        b0  = o2[base + j];
        b1v = o2[base + j + 256];
        b2v = o2[base + j + 512];
        b3  = o2[base + j + 768];
    }

    float dot = 0.f, n1 = 0.f, n2 = 0.f;
    #define ACCUM(A, Bv)                                          \
        dot = fmaf(A.x, Bv.x, dot); dot = fmaf(A.y, Bv.y, dot);   \
        dot = fmaf(A.z, Bv.z, dot); dot = fmaf(A.w, Bv.w, dot);   \
        n1  = fmaf(A.x, A.x, n1);   n1  = fmaf(A.y, A.y, n1);     \
        n1  = fmaf(A.z, A.z, n1);   n1  = fmaf(A.w, A.w, n1);     \
        n2  = fmaf(Bv.x, Bv.x, n2); n2  = fmaf(Bv.y, Bv.y, n2);   \
        n2  = fmaf(Bv.z, Bv.z, n2); n2  = fmaf(Bv.w, Bv.w, n2);
    ACCUM(a0, b0)
    ACCUM(a1v, b1v)
    ACCUM(a2v, b2v)
    ACCUM(a3, b3)
    #undef ACCUM

    // Warp reduction (3 values).
    #pragma unroll
    for (int off = 16; off > 0; off >>= 1) {
        dot += __shfl_xor_sync(0xffffffffu, dot, off);
        n1  += __shfl_xor_sync(0xffffffffu, n1,  off);
        n2  += __shfl_xor_sync(0xffffffffu, n2,  off);
    }

    __shared__ float s_dot[8], s_n1[8], s_n2[8];
    const int wid = threadIdx.x >> 5;
    const int lid = threadIdx.x & 31;
    if (lid == 0) { s_dot[wid] = dot; s_n1[wid] = n1; s_n2[wid] = n2; }
    __syncthreads();
    // Warps 1-7 are done and exit here; only warp 0 runs the tail.

    if (wid == 0) {
        int is_last = 0;
        if (lid == 0) {
            float d = 0.f, q1 = 0.f, q2 = 0.f;
            #pragma unroll
            for (int w = 0; w < 8; ++w) { d += s_dot[w]; q1 += s_n1[w]; q2 += s_n2[w]; }

            const float cosv = d / (sqrtf(q1) * sqrtf(q2));
            const float dist = 0.5f * (1.0f - cosv);      // 1 - 0.5*(1+cos)
            const float t    = (float)tgt[row];
            const float h    = fmaxf(0.0f, 1.0f - sqrtf(dist + 1e-9f));
            g_losses[row] = 0.5f * (t * dist + (1.0f - t) * h * h);

            __threadfence();  // make the store visible before signaling
            is_last = (atomicAdd(&g_count, 1u) == gridDim.x - 1);
        }
        is_last = __shfl_sync(0xffffffffu, is_last, 0);

        if (is_last) {
            // All 8192 stores are visible (fences precede the counter
            // increments we observed). Reduce with L2 (.cg) float4 loads.
            const float4* lp = (const float4*)g_losses;
            const int nf4 = B >> 2;  // 2048
            double acc = 0.0;
            #pragma unroll 8
            for (int i = lid; i < nf4; i += 32) {
                const float4 v = __ldcg(lp + i);
                acc += (double)v.x + (double)v.y + (double)v.z + (double)v.w;
            }
            #pragma unroll
            for (int off = 16; off > 0; off >>= 1)
                acc += __shfl_xor_sync(0xffffffffu, acc, off);

            if (lid == 0) {
                out[0] = (float)(acc / (double)B);
                g_count = 0u;  // reset for next graph replay
            }
        }
    }
}

extern "C" void kernel_launch(void* const* d_in, const int* in_sizes, int n_in,
                              void* d_out, int out_size) {
    const float4* o1 = (const float4*)d_in[0];
    const float4* o2 = (const float4*)d_in[1];
    const int* tgt = (const int*)d_in[2];
    float* out = (float*)d_out;

    const int B = in_sizes[2];           // 8192
    const int D = in_sizes[0] / B;       // 4096
    const int d4 = D / 4;                // 1024

    contrastive_fused_kernel<<<B, 256>>>(o1, o2, tgt, out, B, d4);
}

// round 8
// speedup vs baseline: 1.1902x; 1.1902x over previous
#include <cuda_runtime.h>

// Scalar accumulator in device global memory (no allocations allowed).
// Zero-initialized at module load; finalize_kernel resets it after each
// launch so every graph replay sees a clean state.
__device__ double g_acc;

// One block per row (B=8192, D=4096). Computes dot(a,b), ||a||^2, ||b||^2,
// then the per-row contrastive-loss term, accumulated into g_acc.
// NO fences, NO counters — visibility to finalize_kernel is guaranteed by
// kernel-boundary ordering in the stream.
__global__ void __launch_bounds__(256)
contrastive_row_kernel(const float4* __restrict__ o1,
                       const float4* __restrict__ o2,
                       const int* __restrict__ tgt,  // int32 (jnp int64 w/o x64)
                       int d4 /* D/4 = 1024 */) {
    const int row = blockIdx.x;
    const size_t base = (size_t)row * (size_t)d4;

    // Front-batch all loads: 4 float4 per array per thread -> 8 LDG.128 in flight.
    float4 a0, a1v, a2v, a3;
    float4 b0, b1v, b2v, b3;
    {
        const int j = threadIdx.x;
        a0  = o1[base + j];
        a1v = o1[base + j + 256];
        a2v = o1[base + j + 512];
        a3  = o1[base + j + 768];
        b0  = o2[base + j];
        b1v = o2[base + j + 256];
        b2v = o2[base + j + 512];
        b3  = o2[base + j + 768];
    }

    float dot = 0.f, n1 = 0.f, n2 = 0.f;
    #define ACCUM(A, Bv)                                          \
        dot = fmaf(A.x, Bv.x, dot); dot = fmaf(A.y, Bv.y, dot);   \
        dot = fmaf(A.z, Bv.z, dot); dot = fmaf(A.w, Bv.w, dot);   \
        n1  = fmaf(A.x, A.x, n1);   n1  = fmaf(A.y, A.y, n1);     \
        n1  = fmaf(A.z, A.z, n1);   n1  = fmaf(A.w, A.w, n1);     \
        n2  = fmaf(Bv.x, Bv.x, n2); n2  = fmaf(Bv.y, Bv.y, n2);   \
        n2  = fmaf(Bv.z, Bv.z, n2); n2  = fmaf(Bv.w, Bv.w, n2);
    ACCUM(a0, b0)
    ACCUM(a1v, b1v)
    ACCUM(a2v, b2v)
    ACCUM(a3, b3)
    #undef ACCUM

    // Warp reduction (3 values).
    #pragma unroll
    for (int off = 16; off > 0; off >>= 1) {
        dot += __shfl_xor_sync(0xffffffffu, dot, off);
        n1  += __shfl_xor_sync(0xffffffffu, n1,  off);
        n2  += __shfl_xor_sync(0xffffffffu, n2,  off);
    }

    __shared__ float s_dot[8], s_n1[8], s_n2[8];
    const int wid = threadIdx.x >> 5;
    const int lid = threadIdx.x & 31;
    if (lid == 0) { s_dot[wid] = dot; s_n1[wid] = n1; s_n2[wid] = n2; }
    __syncthreads();

    if (threadIdx.x == 0) {
        float d = 0.f, q1 = 0.f, q2 = 0.f;
        #pragma unroll
        for (int w = 0; w < 8; ++w) { d += s_dot[w]; q1 += s_n1[w]; q2 += s_n2[w]; }

        const float cosv = d / (sqrtf(q1) * sqrtf(q2));
        const float dist = 0.5f * (1.0f - cosv);          // 1 - 0.5*(1+cos)
        const float t    = (float)tgt[row];
        const float h    = fmaxf(0.0f, 1.0f - sqrtf(dist + 1e-9f));
        const float loss = 0.5f * (t * dist + (1.0f - t) * h * h);

        atomicAdd(&g_acc, (double)loss);
    }
}

// Reads the accumulated sum, writes the mean, and resets the accumulator
// for the next launch / graph replay.
__global__ void finalize_kernel(float* __restrict__ out, int B) {
    out[0] = (float)(g_acc / (double)B);
    g_acc = 0.0;
}

extern "C" void kernel_launch(void* const* d_in, const int* in_sizes, int n_in,
                              void* d_out, int out_size) {
    const float4* o1 = (const float4*)d_in[0];
    const float4* o2 = (const float4*)d_in[1];
    const int* tgt = (const int*)d_in[2];
    float* out = (float*)d_out;

    const int B = in_sizes[2];           // 8192
    const int D = in_sizes[0] / B;       // 4096
    const int d4 = D / 4;                // 1024

    contrastive_row_kernel<<<B, 256>>>(o1, o2, tgt, d4);
    finalize_kernel<<<1, 1>>>(out, B);
}